// round 4
// baseline (speedup 1.0000x reference)
#include <cuda_runtime.h>
#include <stdint.h>

// Problem shape (fixed by the reference)
#define NT     4000
#define NS     16
#define NR     512
#define NSR    (NS * NR)          // 8192 columns
#define NCHUNK 10
#define TCHUNK (NT / NCHUNK)      // 400
#define CB_COLS 512               // columns per column-block (float2 x 256 thr)
#define NCB    (NSR / CB_COLS)    // 16 column-blocks
#define WRITERS_PER_CB (NCHUNK * 2)  // 20

// Scratch (device globals; zero-initialized at module load).
// g_part is fully rewritten every launch -> no init kernel needed.
// Counters are monotone across launches; "last arrival" detected via modulo,
// so they never need resetting (graph-replay deterministic).
__device__ unsigned long long g_part[2][NCHUNK][NSR];
__device__ double             g_blocksum[NCB];
__device__ unsigned int       g_cnt[NCB];
__device__ unsigned int       g_done;

__global__ void tt_fused_kernel(const float* __restrict__ x,
                                const float* __restrict__ y,
                                float* __restrict__ out) {
    const int cb    = blockIdx.x;                 // 0..15  column block
    const int chunk = blockIdx.y;                 // 0..9   time chunk
    const int z     = blockIdx.z;                 // 0 = x, 1 = y
    const int t0    = chunk * TCHUNK;
    const int col0  = cb * CB_COLS + threadIdx.x * 2;   // even column

    // ---- Phase 1: chunk-local argmax of v^2, float2-wide coalesced stream ----
    const float2* __restrict__ src = (const float2*)
        ((z == 0 ? x : y) + (size_t)t0 * NSR + cb * CB_COLS) + threadIdx.x;

    float best0 = -1.0f, best1 = -1.0f;
    int   bt0   = t0,    bt1   = t0;
#pragma unroll 8
    for (int i = 0; i < TCHUNK; i++) {
        float2 v  = src[(size_t)i * (NSR / 2)];
        float  a  = v.x * v.x;
        float  b  = v.y * v.y;
        if (a > best0) { best0 = a; bt0 = t0 + i; }  // strict '>' => first max
        if (b > best1) { best1 = b; bt1 = t0 + i; }
    }
    // pack: (float_bits(v^2) << 32) | (NT-1-t). v^2 >= 0 so bits are order-
    // monotone; larger NT-1-t == smaller t wins ties -> argmax-first semantics.
    g_part[z][chunk][col0] =
        ((unsigned long long)__float_as_uint(best0) << 32) |
        (unsigned int)(NT - 1 - bt0);
    g_part[z][chunk][col0 + 1] =
        ((unsigned long long)__float_as_uint(best1) << 32) |
        (unsigned int)(NT - 1 - bt1);

    // ---- Phase 2: last of 20 writer-blocks for this cb reduces it ----
    __shared__ unsigned int s_old;
    __syncthreads();
    if (threadIdx.x == 0) {
        __threadfence();                          // publish g_part stores
        s_old = atomicAdd(&g_cnt[cb], 1u);
    }
    __syncthreads();
    if (s_old % WRITERS_PER_CB != WRITERS_PER_CB - 1) return;

    // This block is the per-column-block reducer (one per cb, 16 total).
    unsigned long long bx0 = 0ull, by0 = 0ull, bx1 = 0ull, by1 = 0ull;
#pragma unroll
    for (int k = 0; k < NCHUNK; k++) {
        unsigned long long px0 = g_part[0][k][col0];
        unsigned long long px1 = g_part[0][k][col0 + 1];
        unsigned long long py0 = g_part[1][k][col0];
        unsigned long long py1 = g_part[1][k][col0 + 1];
        bx0 = (px0 > bx0) ? px0 : bx0;
        bx1 = (px1 > bx1) ? px1 : bx1;
        by0 = (py0 > by0) ? py0 : by0;
        by1 = (py1 > by1) ? py1 : by1;
    }
    const float d0 = (float)((int)(unsigned int)(by0 & 0xffffffffull)
                           - (int)(unsigned int)(bx0 & 0xffffffffull));
    const float d1 = (float)((int)(unsigned int)(by1 & 0xffffffffull)
                           - (int)(unsigned int)(bx1 & 0xffffffffull));
    // note: (NT-1-tx)-(NT-1-ty) = ty-tx; square is sign-invariant.
    double v = (double)d0 * (double)d0 + (double)d1 * (double)d1;

    // block-reduce 256 doubles
    __shared__ double ssum[8];
    const int lane = threadIdx.x & 31;
    const int wid  = threadIdx.x >> 5;
#pragma unroll
    for (int off = 16; off > 0; off >>= 1)
        v += __shfl_down_sync(0xffffffffu, v, off);
    if (lane == 0) ssum[wid] = v;
    __syncthreads();

    __shared__ unsigned int s_old2;
    if (threadIdx.x == 0) {
        double w = 0.0;
#pragma unroll
        for (int i = 0; i < 8; i++) w += ssum[i];
        g_blocksum[cb] = w;
        __threadfence();                          // publish g_blocksum
        s_old2 = atomicAdd(&g_done, 1u);
    }
    __syncthreads();
    if (threadIdx.x != 0) return;
    if (s_old2 % NCB != NCB - 1) return;

    // ---- Phase 3: final arrival sums 16 partials, writes scalar MSE ----
    double s = 0.0;
#pragma unroll
    for (int i = 0; i < NCB; i++) s += g_blocksum[i];
    out[0] = (float)(s * (1.0 / (double)NSR));
}

extern "C" void kernel_launch(void* const* d_in, const int* in_sizes, int n_in,
                              void* d_out, int out_size) {
    const float* x = (const float*)d_in[0];
    const float* y = (const float*)d_in[1];
    float* out = (float*)d_out;
    (void)in_sizes; (void)n_in; (void)out_size;

    dim3 grid(NCB, NCHUNK, 2);
    tt_fused_kernel<<<grid, 256>>>(x, y, out);
}

// round 5
// speedup vs baseline: 1.3591x; 1.3591x over previous
#include <cuda_runtime.h>
#include <stdint.h>

// Problem shape (fixed by the reference)
#define NT     4000
#define NS     16
#define NR     512
#define NSR    (NS * NR)          // 8192 columns
#define NCHUNK 16
#define TCHUNK (NT / NCHUNK)      // 250
#define NCB    (NSR / 256)        // 32 column-blocks
#define WRITERS_PER_CB (NCHUNK * 2)  // 32

// Scratch (device globals; zero-initialized at module load).
// g_part is fully rewritten every launch -> no init kernel needed.
// Counters are monotone across launches; "last arrival" detected via modulo,
// so they never need resetting (graph-replay deterministic).
__device__ unsigned long long g_part[2][NCHUNK][NSR];
__device__ double             g_blocksum[NCB];
__device__ unsigned int       g_cnt[NCB];
__device__ unsigned int       g_done;

__global__ void __launch_bounds__(256, 8)
tt_fused_kernel(const float* __restrict__ x,
                const float* __restrict__ y,
                float* __restrict__ out) {
    const int cb    = blockIdx.x;               // 0..31  column block
    const int chunk = blockIdx.y;               // 0..15  time chunk
    const int z     = blockIdx.z;               // 0 = x, 1 = y
    const int col   = cb * 256 + threadIdx.x;   // 0..8191
    const int t0    = chunk * TCHUNK;

    // ---- Phase 1: chunk-local argmax of v^2 (scalar coalesced stream;
    //      scalar loads keep in-flight data at 8 regs -> full MLP at 32 regs) ----
    const float* __restrict__ src =
        (z == 0 ? x : y) + (size_t)t0 * NSR + col;

    float best = -1.0f;
    int   bt   = t0;
#pragma unroll 8
    for (int i = 0; i < TCHUNK; i++) {
        float v  = src[(size_t)i * NSR];
        float v2 = v * v;
        if (v2 > best) { best = v2; bt = t0 + i; }   // strict '>' => first max
    }
    // pack: (float_bits(v^2) << 32) | (NT-1-t). v^2 >= 0 so bits are order-
    // monotone; larger NT-1-t == smaller t wins ties -> argmax-first semantics.
    g_part[z][chunk][col] =
        ((unsigned long long)__float_as_uint(best) << 32) |
        (unsigned int)(NT - 1 - bt);

    // ---- Phase 2: last of 32 writer-blocks for this cb reduces it ----
    __shared__ unsigned int s_old;
    __syncthreads();
    if (threadIdx.x == 0) {
        __threadfence();                          // publish g_part stores
        s_old = atomicAdd(&g_cnt[cb], 1u);
    }
    __syncthreads();
    if (s_old % WRITERS_PER_CB != WRITERS_PER_CB - 1) return;

    // This block is the per-column-block reducer (one per cb, 32 total).
    unsigned long long bx = 0ull, by = 0ull;
#pragma unroll
    for (int k = 0; k < NCHUNK; k++) {
        unsigned long long px = g_part[0][k][col];
        unsigned long long py = g_part[1][k][col];
        bx = (px > bx) ? px : bx;
        by = (py > by) ? py : by;
    }
    // (NT-1-tx) - (NT-1-ty) = ty - tx; square is sign-invariant.
    const float d = (float)((int)(unsigned int)(by & 0xffffffffull)
                          - (int)(unsigned int)(bx & 0xffffffffull));
    double v = (double)d * (double)d;

    // block-reduce 256 doubles
    __shared__ double ssum[8];
    const int lane = threadIdx.x & 31;
    const int wid  = threadIdx.x >> 5;
#pragma unroll
    for (int off = 16; off > 0; off >>= 1)
        v += __shfl_down_sync(0xffffffffu, v, off);
    if (lane == 0) ssum[wid] = v;
    __syncthreads();

    __shared__ unsigned int s_old2;
    if (threadIdx.x == 0) {
        double w = 0.0;
#pragma unroll
        for (int i = 0; i < 8; i++) w += ssum[i];
        g_blocksum[cb] = w;
        __threadfence();                          // publish g_blocksum
        s_old2 = atomicAdd(&g_done, 1u);
    }
    __syncthreads();
    if (threadIdx.x != 0) return;
    if (s_old2 % NCB != NCB - 1) return;

    // ---- Phase 3: final arrival sums 32 partials, writes scalar MSE ----
    double s = 0.0;
#pragma unroll
    for (int i = 0; i < NCB; i++) s += g_blocksum[i];
    out[0] = (float)(s * (1.0 / (double)NSR));
}

extern "C" void kernel_launch(void* const* d_in, const int* in_sizes, int n_in,
                              void* d_out, int out_size) {
    const float* x = (const float*)d_in[0];
    const float* y = (const float*)d_in[1];
    float* out = (float*)d_out;
    (void)in_sizes; (void)n_in; (void)out_size;

    dim3 grid(NCB, NCHUNK, 2);
    tt_fused_kernel<<<grid, 256>>>(x, y, out);
}